// round 1
// baseline (speedup 1.0000x reference)
#include <cuda_runtime.h>
#include <math.h>

#define BATCH 2
#define SEQ   2048
#define NH    16
#define DHEAD 64
#define DMODEL 1024
#define MROWS (BATCH*SEQ)   // 4096

// ---------------- scratch (device globals; no allocation allowed) ----------
__device__ float g_q[BATCH*SEQ*DMODEL];
__device__ float g_k[BATCH*SEQ*DMODEL];
__device__ float g_v[BATCH*SEQ*DMODEL];
__device__ float g_ctx[BATCH*SEQ*DMODEL];

// ======================= SGEMM: C = A[M,K] @ W[K,N] + bias =================
#define BM 128
#define BN 128
#define BK 16

__global__ __launch_bounds__(256, 2)
void sgemm_bias_kernel(const float* __restrict__ A,
                       const float* __restrict__ Bw,
                       const float* __restrict__ bias,
                       float* __restrict__ C,
                       int M, int N, int K)
{
    __shared__ float As[BK][BM];   // transposed A tile: As[k][m]
    __shared__ float Bs[BK][BN];   // Bs[k][n]

    const int t  = threadIdx.x;
    const int tx = t & 15;         // 0..15 -> 8 cols
    const int ty = t >> 4;         // 0..15 -> 8 rows
    const int row0 = blockIdx.y * BM;
    const int col0 = blockIdx.x * BN;

    float acc[8][8];
#pragma unroll
    for (int i = 0; i < 8; i++)
#pragma unroll
        for (int j = 0; j < 8; j++) acc[i][j] = 0.f;

    for (int k0 = 0; k0 < K; k0 += BK) {
        // load A tile: 128x16 floats = 512 float4, 2 per thread
#pragma unroll
        for (int q = 0; q < 2; q++) {
            int f  = t + q * 256;        // float4 id 0..511
            int r  = f >> 2;             // row in tile 0..127
            int c4 = (f & 3) << 2;       // 0,4,8,12
            float4 a4 = *(const float4*)(A + (size_t)(row0 + r) * K + k0 + c4);
            As[c4 + 0][r] = a4.x;
            As[c4 + 1][r] = a4.y;
            As[c4 + 2][r] = a4.z;
            As[c4 + 3][r] = a4.w;
        }
        // load B tile: 16x128 floats = 512 float4, 2 per thread
#pragma unroll
        for (int q = 0; q < 2; q++) {
            int f  = t + q * 256;
            int r  = f >> 5;             // 0..15
            int c4 = (f & 31) << 2;      // 0..124
            *(float4*)&Bs[r][c4] =
                *(const float4*)(Bw + (size_t)(k0 + r) * N + col0 + c4);
        }
        __syncthreads();

#pragma unroll
        for (int kk = 0; kk < BK; kk++) {
            float a[8], b[8];
            *(float4*)(a)     = *(float4*)&As[kk][ty * 8];
            *(float4*)(a + 4) = *(float4*)&As[kk][ty * 8 + 4];
            *(float4*)(b)     = *(float4*)&Bs[kk][tx * 8];
            *(float4*)(b + 4) = *(float4*)&Bs[kk][tx * 8 + 4];
#pragma unroll
            for (int i = 0; i < 8; i++)
#pragma unroll
                for (int j = 0; j < 8; j++)
                    acc[i][j] += a[i] * b[j];
        }
        __syncthreads();
    }

    float bv[8];
#pragma unroll
    for (int j = 0; j < 8; j++) bv[j] = bias[col0 + tx * 8 + j];

#pragma unroll
    for (int i = 0; i < 8; i++) {
        int row = row0 + ty * 8 + i;
        float* Cp = C + (size_t)row * N + col0 + tx * 8;
        float4 o0, o1;
        o0.x = acc[i][0] + bv[0];  o0.y = acc[i][1] + bv[1];
        o0.z = acc[i][2] + bv[2];  o0.w = acc[i][3] + bv[3];
        o1.x = acc[i][4] + bv[4];  o1.y = acc[i][5] + bv[5];
        o1.z = acc[i][6] + bv[6];  o1.w = acc[i][7] + bv[7];
        *(float4*)(Cp)     = o0;
        *(float4*)(Cp + 4) = o1;
    }
}

// ======================= Flash attention (fp32) ============================
// One CTA per (b, h, 128 q-rows). KV tiles of 64. Online softmax.
#define BQ  128
#define BKV 64
#define QT_ST 128           // Qt[d][r]   : 64 x 128
#define KT_ST 68            // Kt[d][j]   : 64 x 64 (+pad)
#define V_ST  68            // Vs[j][d]   : 64 x 64 (+pad)
#define S_ST  65            // Ss[r][j]   : 128 x 64 (+pad, odd stride)

#define ATTN_SMEM_FLOATS (64*QT_ST + 64*KT_ST + 64*V_ST + BQ*S_ST + 3*BQ)

__global__ __launch_bounds__(256, 2)
void attn_kernel(const float* __restrict__ Q,
                 const float* __restrict__ K,
                 const float* __restrict__ V,
                 float* __restrict__ ctx)
{
    extern __shared__ float sm[];
    float* Qt   = sm;                    // 64*128
    float* Kt   = Qt + 64 * QT_ST;       // 64*68
    float* Vs   = Kt + 64 * KT_ST;       // 64*68
    float* Ss   = Vs + 64 * V_ST;        // 128*65
    float* mrow = Ss + BQ * S_ST;        // 128
    float* lrow = mrow + BQ;             // 128
    float* cfac = lrow + BQ;             // 128

    const int t  = threadIdx.x;
    const int q0 = blockIdx.x * BQ;
    const int h  = blockIdx.y;
    const int b  = blockIdx.z;

    const float* Qg = Q + ((size_t)(b * SEQ + q0)) * DMODEL + h * DHEAD;
    const float* Kg = K + ((size_t)(b * SEQ)) * DMODEL + h * DHEAD;
    const float* Vg = V + ((size_t)(b * SEQ)) * DMODEL + h * DHEAD;

    // ---- load Q tile transposed: Qt[d][r], 128 rows x 64 cols = 2048 float4
#pragma unroll
    for (int q = 0; q < 8; q++) {
        int f  = t + q * 256;       // 0..2047
        int r  = f >> 4;            // 0..127
        int c4 = (f & 15) << 2;     // 0..60
        float4 v4 = *(const float4*)(Qg + (size_t)r * DMODEL + c4);
        Qt[(c4 + 0) * QT_ST + r] = v4.x;
        Qt[(c4 + 1) * QT_ST + r] = v4.y;
        Qt[(c4 + 2) * QT_ST + r] = v4.z;
        Qt[(c4 + 3) * QT_ST + r] = v4.w;
    }
    if (t < BQ) { mrow[t] = -1e30f; lrow[t] = 0.f; }

    const int tx = t & 15, ty = t >> 4;   // scores layout: 8 rows x 4 cols
    const int tr = t & 31, tc = t >> 5;   // PV layout: rows tr+32i, cols tc*8..

    float acc[4][8];
#pragma unroll
    for (int i = 0; i < 4; i++)
#pragma unroll
        for (int j = 0; j < 8; j++) acc[i][j] = 0.f;

    for (int kv = 0; kv < SEQ; kv += BKV) {
        __syncthreads();   // previous PV done reading Ss/Vs; Qt load done (iter 0)

        // ---- load K tile transposed Kt[d][j], V tile Vs[j][d]: 64x64 each
#pragma unroll
        for (int q = 0; q < 4; q++) {
            int f  = t + q * 256;     // 0..1023
            int r  = f >> 4;          // kv row 0..63
            int c4 = (f & 15) << 2;   // 0..60
            float4 k4 = *(const float4*)(Kg + (size_t)(kv + r) * DMODEL + c4);
            Kt[(c4 + 0) * KT_ST + r] = k4.x;
            Kt[(c4 + 1) * KT_ST + r] = k4.y;
            Kt[(c4 + 2) * KT_ST + r] = k4.z;
            Kt[(c4 + 3) * KT_ST + r] = k4.w;
            float4 v4 = *(const float4*)(Vg + (size_t)(kv + r) * DMODEL + c4);
            *(float4*)&Vs[r * V_ST + c4] = v4;
        }
        __syncthreads();

        // ---- scores: S = Q @ K^T * 0.125 ; per-thread 8 rows x 4 cols
        {
            float sacc[8][4];
#pragma unroll
            for (int i = 0; i < 8; i++)
#pragma unroll
                for (int j = 0; j < 4; j++) sacc[i][j] = 0.f;

#pragma unroll 4
            for (int kk = 0; kk < DHEAD; kk++) {
                float a[8];
                *(float4*)(a)     = *(float4*)&Qt[kk * QT_ST + ty * 8];
                *(float4*)(a + 4) = *(float4*)&Qt[kk * QT_ST + ty * 8 + 4];
                float4 bb = *(float4*)&Kt[kk * KT_ST + tx * 4];
                float bvv[4] = {bb.x, bb.y, bb.z, bb.w};
#pragma unroll
                for (int i = 0; i < 8; i++)
#pragma unroll
                    for (int j = 0; j < 4; j++)
                        sacc[i][j] += a[i] * bvv[j];
            }
#pragma unroll
            for (int i = 0; i < 8; i++)
#pragma unroll
                for (int j = 0; j < 4; j++)
                    Ss[(ty * 8 + i) * S_ST + tx * 4 + j] = sacc[i][j] * 0.125f;
        }
        __syncthreads();

        // ---- online softmax, one thread per row
        if (t < BQ) {
            float mold = mrow[t];
            float mx = mold;
#pragma unroll 8
            for (int c = 0; c < BKV; c++)
                mx = fmaxf(mx, Ss[t * S_ST + c]);
            float cf = __expf(mold - mx);
            float sum = 0.f;
#pragma unroll 8
            for (int c = 0; c < BKV; c++) {
                float e = __expf(Ss[t * S_ST + c] - mx);
                Ss[t * S_ST + c] = e;
                sum += e;
            }
            lrow[t] = lrow[t] * cf + sum;
            mrow[t] = mx;
            cfac[t] = cf;
        }
        __syncthreads();

        // ---- PV: acc = acc*cf + P @ V ; rows tr+32i, cols tc*8..tc*8+7
        float cfl[4];
#pragma unroll
        for (int i = 0; i < 4; i++) cfl[i] = cfac[tr + 32 * i];
#pragma unroll
        for (int i = 0; i < 4; i++)
#pragma unroll
            for (int j = 0; j < 8; j++) acc[i][j] *= cfl[i];

#pragma unroll 4
        for (int j = 0; j < BKV; j++) {
            float p[4];
#pragma unroll
            for (int i = 0; i < 4; i++)
                p[i] = Ss[(tr + 32 * i) * S_ST + j];
            float4 v0 = *(float4*)&Vs[j * V_ST + tc * 8];
            float4 v1 = *(float4*)&Vs[j * V_ST + tc * 8 + 4];
#pragma unroll
            for (int i = 0; i < 4; i++) {
                acc[i][0] += p[i] * v0.x;  acc[i][1] += p[i] * v0.y;
                acc[i][2] += p[i] * v0.z;  acc[i][3] += p[i] * v0.w;
                acc[i][4] += p[i] * v1.x;  acc[i][5] += p[i] * v1.y;
                acc[i][6] += p[i] * v1.z;  acc[i][7] += p[i] * v1.w;
            }
        }
    }

    // ---- epilogue: divide by l, write ctx in [b][s][h*DH+d] layout
#pragma unroll
    for (int i = 0; i < 4; i++) {
        int row = tr + 32 * i;
        float inv = 1.0f / lrow[row];
        float* o = ctx + ((size_t)(b * SEQ + q0 + row)) * DMODEL + h * DHEAD + tc * 8;
        float4 o0, o1;
        o0.x = acc[i][0] * inv;  o0.y = acc[i][1] * inv;
        o0.z = acc[i][2] * inv;  o0.w = acc[i][3] * inv;
        o1.x = acc[i][4] * inv;  o1.y = acc[i][5] * inv;
        o1.z = acc[i][6] * inv;  o1.w = acc[i][7] * inv;
        *(float4*)(o)     = o0;
        *(float4*)(o + 4) = o1;
    }
}

// =========================== launch ========================================
extern "C" void kernel_launch(void* const* d_in, const int* in_sizes, int n_in,
                              void* d_out, int out_size)
{
    (void)in_sizes; (void)n_in; (void)out_size;

    const float* qx = (const float*)d_in[0];
    const float* kx = (const float*)d_in[1];
    const float* vx = (const float*)d_in[2];
    const float* Wq = (const float*)d_in[3];
    const float* bq = (const float*)d_in[4];
    const float* Wk = (const float*)d_in[5];
    const float* bk = (const float*)d_in[6];
    const float* Wv = (const float*)d_in[7];
    const float* bv = (const float*)d_in[8];
    const float* Wo = (const float*)d_in[9];
    const float* bo = (const float*)d_in[10];
    float* out = (float*)d_out;

    float *gq, *gk, *gv, *gctx;
    cudaGetSymbolAddress((void**)&gq,   g_q);
    cudaGetSymbolAddress((void**)&gk,   g_k);
    cudaGetSymbolAddress((void**)&gv,   g_v);
    cudaGetSymbolAddress((void**)&gctx, g_ctx);

    const int attn_smem = ATTN_SMEM_FLOATS * 4;  // ~102.4 KB
    cudaFuncSetAttribute(attn_kernel,
                         cudaFuncAttributeMaxDynamicSharedMemorySize, attn_smem);

    dim3 gthreads(256);
    dim3 ggrid(DMODEL / BN, MROWS / BM);   // (8, 32)

    // QKV projections
    sgemm_bias_kernel<<<ggrid, gthreads>>>(qx, Wq, bq, gq, MROWS, DMODEL, DMODEL);
    sgemm_bias_kernel<<<ggrid, gthreads>>>(kx, Wk, bk, gk, MROWS, DMODEL, DMODEL);
    sgemm_bias_kernel<<<ggrid, gthreads>>>(vx, Wv, bv, gv, MROWS, DMODEL, DMODEL);

    // attention
    dim3 agrid(SEQ / BQ, NH, BATCH);       // (16, 16, 2)
    attn_kernel<<<agrid, 256, attn_smem>>>(gq, gk, gv, gctx);

    // output projection
    sgemm_bias_kernel<<<ggrid, gthreads>>>(gctx, Wo, bo, out, MROWS, DMODEL, DMODEL);
}

// round 4
// speedup vs baseline: 1.3345x; 1.3345x over previous
#include <cuda_runtime.h>
#include <cuda_bf16.h>
#include <cstdint>
#include <math.h>

#define BATCH 2
#define SEQ   2048
#define NH    16
#define DHEAD 64
#define DMODEL 1024
#define MROWS (BATCH*SEQ)   // 4096

// ---------------- scratch (device globals; no allocation allowed) ----------
__device__ float g_q[MROWS*DMODEL];
__device__ float g_k[MROWS*DMODEL];
__device__ float g_v[MROWS*DMODEL];
__device__ float g_ctx[MROWS*DMODEL];
__device__ __nv_bfloat16 g_act_hi[MROWS*DMODEL];
__device__ __nv_bfloat16 g_act_lo[MROWS*DMODEL];
__device__ __nv_bfloat16 g_wt_hi[DMODEL*DMODEL];   // W^T layout [N][K]
__device__ __nv_bfloat16 g_wt_lo[DMODEL*DMODEL];

// ======================= helpers ===========================================
__device__ __forceinline__ uint32_t s2u(const void* p) {
    uint32_t a;
    asm("{ .reg .u64 t; cvta.to.shared.u64 t, %1; cvt.u32.u64 %0, t; }"
        : "=r"(a) : "l"(p));
    return a;
}
__device__ __forceinline__ void cp16(uint32_t d, const void* s) {
    asm volatile("cp.async.cg.shared.global [%0], [%1], 16;\n" :: "r"(d), "l"(s));
}
__device__ __forceinline__ void mma_bf16(float* d,
                                         uint32_t a0, uint32_t a1,
                                         uint32_t a2, uint32_t a3,
                                         uint32_t b0, uint32_t b1) {
    asm volatile(
        "mma.sync.aligned.m16n8k16.row.col.f32.bf16.bf16.f32 "
        "{%0,%1,%2,%3}, {%4,%5,%6,%7}, {%8,%9}, {%0,%1,%2,%3};"
        : "+f"(d[0]), "+f"(d[1]), "+f"(d[2]), "+f"(d[3])
        : "r"(a0), "r"(a1), "r"(a2), "r"(a3), "r"(b0), "r"(b1));
}

// ======================= split conversion kernels ==========================
__global__ __launch_bounds__(256)
void split_kernel(const float* __restrict__ X,
                  __nv_bfloat16* __restrict__ hi,
                  __nv_bfloat16* __restrict__ lo, int n4)
{
    int i = blockIdx.x * 256 + threadIdx.x;
    if (i >= n4) return;
    float4 v = ((const float4*)X)[i];
    float f[4] = {v.x, v.y, v.z, v.w};
    __nv_bfloat16 h[4], l[4];
#pragma unroll
    for (int j = 0; j < 4; j++) {
        h[j] = __float2bfloat16(f[j]);
        l[j] = __float2bfloat16(f[j] - __bfloat162float(h[j]));
    }
    __nv_bfloat162 ph0, ph1, pl0, pl1;
    ph0.x = h[0]; ph0.y = h[1];  ph1.x = h[2]; ph1.y = h[3];
    pl0.x = l[0]; pl0.y = l[1];  pl1.x = l[2]; pl1.y = l[3];
    ((__nv_bfloat162*)hi)[2*i]   = ph0;
    ((__nv_bfloat162*)hi)[2*i+1] = ph1;
    ((__nv_bfloat162*)lo)[2*i]   = pl0;
    ((__nv_bfloat162*)lo)[2*i+1] = pl1;
}

// transpose + split: W[K,N] -> WT[N,K] as bf16 hi/lo
__global__ __launch_bounds__(256)
void wtsplit_kernel(const float* __restrict__ W,
                    __nv_bfloat16* __restrict__ wth,
                    __nv_bfloat16* __restrict__ wtl)
{
    __shared__ float tile[32][33];
    int tx = threadIdx.x & 31, ty = threadIdx.x >> 5;  // 32x8
    int n0 = blockIdx.x * 32, k0 = blockIdx.y * 32;
#pragma unroll
    for (int i = 0; i < 4; i++)
        tile[ty + 8*i][tx] = W[(size_t)(k0 + ty + 8*i) * DMODEL + n0 + tx];
    __syncthreads();
#pragma unroll
    for (int i = 0; i < 4; i++) {
        float x = tile[tx][ty + 8*i];
        __nv_bfloat16 h = __float2bfloat16(x);
        __nv_bfloat16 l = __float2bfloat16(x - __bfloat162float(h));
        size_t o = (size_t)(n0 + ty + 8*i) * DMODEL + k0 + tx;
        wth[o] = h;
        wtl[o] = l;
    }
}

// ======================= HMMA GEMM: C = A @ W^T + bias =====================
// A [M,K] K-major bf16 hi/lo; B = W^T [N,K] K-major bf16 hi/lo; fp32 acc.
// CTA 128x128, 8 warps (2x4), warp tile 64x32, K-chunk 32, double-buffered.
#define KC 32
#define AST 40                          // bf16 stride (pad 8) -> conflict-free
#define TILE_B (128*AST*2)              // 10240 bytes per tile
#define STAGE_B (4*TILE_B)              // Ah,Al,Bh,Bl = 40960
#define GEMM_SMEM (2*STAGE_B)           // 81920
#define NCH (DMODEL/KC)                 // 32

__global__ __launch_bounds__(256)
void gemm_mma_kernel(const __nv_bfloat16* __restrict__ Ah,
                     const __nv_bfloat16* __restrict__ Al,
                     const __nv_bfloat16* __restrict__ Bh,
                     const __nv_bfloat16* __restrict__ Bl,
                     const float* __restrict__ bias,
                     float* __restrict__ C)
{
    extern __shared__ char smem[];
    const uint32_t sb = s2u(smem);
    const int t = threadIdx.x, w = t >> 5, l = t & 31;
    const int row0 = blockIdx.y * 128, col0 = blockIdx.x * 128;
    const int wm = (w & 1) * 64;        // warp M offset in tile
    const int wn = (w >> 1) * 32;       // warp N offset in tile

    float acc[4][4][4];
#pragma unroll
    for (int mt = 0; mt < 4; mt++)
#pragma unroll
        for (int nt = 0; nt < 4; nt++)
#pragma unroll
            for (int k = 0; k < 4; k++) acc[mt][nt][k] = 0.f;

    // ---------------- stage loader ----------------
    auto load_stage = [&](int c, int st) {
        const uint32_t base = sb + st * STAGE_B;
        const int kc = c * KC;
#pragma unroll
        for (int i = 0; i < 2; i++) {
            int u = t + i * 256;                 // 0..511
            int r = u >> 2, j = u & 3;           // row, 16B-chunk
            uint32_t dso = (uint32_t)(r * 80 + j * 16);
            size_t ga = (size_t)(row0 + r) * DMODEL + kc + j * 8;
            size_t gb = (size_t)(col0 + r) * DMODEL + kc + j * 8;
            cp16(base + dso,              Ah + ga);
            cp16(base + TILE_B + dso,     Al + ga);
            cp16(base + 2*TILE_B + dso,   Bh + gb);
            cp16(base + 3*TILE_B + dso,   Bl + gb);
        }
        asm volatile("cp.async.commit_group;\n" ::: "memory");
    };

    load_stage(0, 0);

    const int ar = l >> 2;            // 0..7 row in 8-row group
    const int ak = (l & 3) * 2;       // 0..6 k offset

    for (int c = 0; c < NCH; c++) {
        if (c + 1 < NCH) load_stage(c + 1, (c + 1) & 1);
        if (c + 1 < NCH)
            asm volatile("cp.async.wait_group 1;\n" ::: "memory");
        else
            asm volatile("cp.async.wait_group 0;\n" ::: "memory");
        __syncthreads();

        const char* stg = smem + (c & 1) * STAGE_B;
        const __nv_bfloat16* sAh = (const __nv_bfloat16*)(stg);
        const __nv_bfloat16* sAl = (const __nv_bfloat16*)(stg + TILE_B);
        const __nv_bfloat16* sBh = (const __nv_bfloat16*)(stg + 2*TILE_B);
        const __nv_bfloat16* sBl = (const __nv_bfloat16*)(stg + 3*TILE_B);

#pragma unroll
        for (int ks = 0; ks < KC; ks += 16) {
            uint32_t aH[4][4], aL[4][4], bH[4][2], bL[4][2];
#pragma unroll
            for (int mt = 0; mt < 4; mt++) {
                int r = wm + mt * 16 + ar;
                const uint32_t* p0 = (const uint32_t*)&sAh[r * AST + ks + ak];
                const uint32_t* p1 = (const uint32_t*)&sAh[(r + 8) * AST + ks + ak];
                aH[mt][0] = p0[0];  aH[mt][1] = p1[0];
                aH[mt][2] = p0[4];  aH[mt][3] = p1[4];
                const uint32_t* q0 = (const uint32_t*)&sAl[r * AST + ks + ak];
                const uint32_t* q1 = (const uint32_t*)&sAl[(r + 8) * AST + ks + ak];
                aL[mt][0] = q0[0];  aL[mt][1] = q1[0];
                aL[mt][2] = q0[4];  aL[mt][3] = q1[4];
            }
#pragma unroll
            for (int nt = 0; nt < 4; nt++) {
                int n = wn + nt * 8 + ar;
                const uint32_t* p = (const uint32_t*)&sBh[n * AST + ks + ak];
                bH[nt][0] = p[0];  bH[nt][1] = p[4];
                const uint32_t* q = (const uint32_t*)&sBl[n * AST + ks + ak];
                bL[nt][0] = q[0];  bL[nt][1] = q[4];
            }
#pragma unroll
            for (int mt = 0; mt < 4; mt++)
#pragma unroll
                for (int nt = 0; nt < 4; nt++) {
                    mma_bf16(acc[mt][nt], aH[mt][0], aH[mt][1], aH[mt][2], aH[mt][3],
                             bH[nt][0], bH[nt][1]);
                    mma_bf16(acc[mt][nt], aL[mt][0], aL[mt][1], aL[mt][2], aL[mt][3],
                             bH[nt][0], bH[nt][1]);
                    mma_bf16(acc[mt][nt], aH[mt][0], aH[mt][1], aH[mt][2], aH[mt][3],
                             bL[nt][0], bL[nt][1]);
                }
        }
        __syncthreads();
    }

    // ---------------- epilogue: bias + store ----------------
#pragma unroll
    for (int mt = 0; mt < 4; mt++) {
        int gr0 = row0 + wm + mt * 16 + ar;
#pragma unroll
        for (int nt = 0; nt < 4; nt++) {
            int gc = col0 + wn + nt * 8 + (l & 3) * 2;
            float b0 = bias[gc], b1 = bias[gc + 1];
            float2 o0 = make_float2(acc[mt][nt][0] + b0, acc[mt][nt][1] + b1);
            float2 o1 = make_float2(acc[mt][nt][2] + b0, acc[mt][nt][3] + b1);
            *(float2*)(C + (size_t)gr0 * DMODEL + gc)       = o0;
            *(float2*)(C + (size_t)(gr0 + 8) * DMODEL + gc) = o1;
        }
    }
}

// ======================= Flash attention (fp32, unchanged) =================
#define BQ  128
#define BKV 64
#define QT_ST 128
#define KT_ST 68
#define V_ST  68
#define S_ST  65
#define ATTN_SMEM_FLOATS (64*QT_ST + 64*KT_ST + 64*V_ST + BQ*S_ST + 3*BQ)

__global__ __launch_bounds__(256, 2)
void attn_kernel(const float* __restrict__ Q,
                 const float* __restrict__ K,
                 const float* __restrict__ V,
                 float* __restrict__ ctx)
{
    extern __shared__ float sm[];
    float* Qt   = sm;
    float* Kt   = Qt + 64 * QT_ST;
    float* Vs   = Kt + 64 * KT_ST;
    float* Ss   = Vs + 64 * V_ST;
    float* mrow = Ss + BQ * S_ST;
    float* lrow = mrow + BQ;
    float* cfac = lrow + BQ;

    const int t  = threadIdx.x;
    const int q0 = blockIdx.x * BQ;
    const int h  = blockIdx.y;
    const int b  = blockIdx.z;

    const float* Qg = Q + ((size_t)(b * SEQ + q0)) * DMODEL + h * DHEAD;
    const float* Kg = K + ((size_t)(b * SEQ)) * DMODEL + h * DHEAD;
    const float* Vg = V + ((size_t)(b * SEQ)) * DMODEL + h * DHEAD;

#pragma unroll
    for (int q = 0; q < 8; q++) {
        int f  = t + q * 256;
        int r  = f >> 4;
        int c4 = (f & 15) << 2;
        float4 v4 = *(const float4*)(Qg + (size_t)r * DMODEL + c4);
        Qt[(c4 + 0) * QT_ST + r] = v4.x;
        Qt[(c4 + 1) * QT_ST + r] = v4.y;
        Qt[(c4 + 2) * QT_ST + r] = v4.z;
        Qt[(c4 + 3) * QT_ST + r] = v4.w;
    }
    if (t < BQ) { mrow[t] = -1e30f; lrow[t] = 0.f; }

    const int tx = t & 15, ty = t >> 4;
    const int tr = t & 31, tc = t >> 5;

    float acc[4][8];
#pragma unroll
    for (int i = 0; i < 4; i++)
#pragma unroll
        for (int j = 0; j < 8; j++) acc[i][j] = 0.f;

    for (int kv = 0; kv < SEQ; kv += BKV) {
        __syncthreads();

#pragma unroll
        for (int q = 0; q < 4; q++) {
            int f  = t + q * 256;
            int r  = f >> 4;
            int c4 = (f & 15) << 2;
            float4 k4 = *(const float4*)(Kg + (size_t)(kv + r) * DMODEL + c4);
            Kt[(c4 + 0) * KT_ST + r] = k4.x;
            Kt[(c4 + 1) * KT_ST + r] = k4.y;
            Kt[(c4 + 2) * KT_ST + r] = k4.z;
            Kt[(c4 + 3) * KT_ST + r] = k4.w;
            float4 v4 = *(const float4*)(Vg + (size_t)(kv + r) * DMODEL + c4);
            *(float4*)&Vs[r * V_ST + c4] = v4;
        }
        __syncthreads();

        {
            float sacc[8][4];
#pragma unroll
            for (int i = 0; i < 8; i++)
#pragma unroll
                for (int j = 0; j < 4; j++) sacc[i][j] = 0.f;

#pragma unroll 4
            for (int kk = 0; kk < DHEAD; kk++) {
                float a[8];
                *(float4*)(a)     = *(float4*)&Qt[kk * QT_ST + ty * 8];
                *(float4*)(a + 4) = *(float4*)&Qt[kk * QT_ST + ty * 8 + 4];
                float4 bb = *(float4*)&Kt[kk * KT_ST + tx * 4];
                float bvv[4] = {bb.x, bb.y, bb.z, bb.w};
#pragma unroll
                for (int i = 0; i < 8; i++)
#pragma unroll
                    for (int j = 0; j < 4; j++)
                        sacc[i][j] += a[i] * bvv[j];
            }
#pragma unroll
            for (int i = 0; i < 8; i++)
#pragma unroll
                for (int j = 0; j < 4; j++)
                    Ss[(ty * 8 + i) * S_ST + tx * 4 + j] = sacc[i][j] * 0.125f;
        }
        __syncthreads();

        if (t < BQ) {
            float mold = mrow[t];
            float mx = mold;
#pragma unroll 8
            for (int c = 0; c < BKV; c++)
                mx = fmaxf(mx, Ss[t * S_ST + c]);
            float cf = __expf(mold - mx);
            float sum = 0.f;
#pragma unroll 8
            for (int c = 0; c < BKV; c++) {
                float e = __expf(Ss[t * S_ST + c] - mx);
                Ss[t * S_ST + c] = e;
                sum += e;
            }
            lrow[t] = lrow[t] * cf + sum;
            mrow[t] = mx;
            cfac[t] = cf;
        }
        __syncthreads();

        float cfl[4];
#pragma unroll
        for (int i = 0; i < 4; i++) cfl[i] = cfac[tr + 32 * i];
#pragma unroll
        for (int i = 0; i < 4; i++)
#pragma unroll
            for (int j = 0; j < 8; j++) acc[i][j] *= cfl[i];

#pragma unroll 4
        for (int j = 0; j < BKV; j++) {
            float p[4];
#pragma unroll
            for (int i = 0; i < 4; i++)
                p[i] = Ss[(tr + 32 * i) * S_ST + j];
            float4 v0 = *(float4*)&Vs[j * V_ST + tc * 8];
            float4 v1 = *(float4*)&Vs[j * V_ST + tc * 8 + 4];
#pragma unroll
            for (int i = 0; i < 4; i++) {
                acc[i][0] += p[i] * v0.x;  acc[i][1] += p[i] * v0.y;
                acc[i][2] += p[i] * v0.z;  acc[i][3] += p[i] * v0.w;
                acc[i][4] += p[i] * v1.x;  acc[i][5] += p[i] * v1.y;
                acc[i][6] += p[i] * v1.z;  acc[i][7] += p[i] * v1.w;
            }
        }
    }

#pragma unroll
    for (int i = 0; i < 4; i++) {
        int row = tr + 32 * i;
        float inv = 1.0f / lrow[row];
        float* o = ctx + ((size_t)(b * SEQ + q0 + row)) * DMODEL + h * DHEAD + tc * 8;
        float4 o0, o1;
        o0.x = acc[i][0] * inv;  o0.y = acc[i][1] * inv;
        o0.z = acc[i][2] * inv;  o0.w = acc[i][3] * inv;
        o1.x = acc[i][4] * inv;  o1.y = acc[i][5] * inv;
        o1.z = acc[i][6] * inv;  o1.w = acc[i][7] * inv;
        *(float4*)(o)     = o0;
        *(float4*)(o + 4) = o1;
    }
}

// =========================== launch ========================================
extern "C" void kernel_launch(void* const* d_in, const int* in_sizes, int n_in,
                              void* d_out, int out_size)
{
    (void)in_sizes; (void)n_in; (void)out_size;

    const float* qx = (const float*)d_in[0];
    const float* kx = (const float*)d_in[1];
    const float* vx = (const float*)d_in[2];
    const float* Wq = (const float*)d_in[3];
    const float* bq = (const float*)d_in[4];
    const float* Wk = (const float*)d_in[5];
    const float* bk = (const float*)d_in[6];
    const float* Wv = (const float*)d_in[7];
    const float* bv = (const float*)d_in[8];
    const float* Wo = (const float*)d_in[9];
    const float* bo = (const float*)d_in[10];
    float* out = (float*)d_out;

    float *gq, *gk, *gv, *gctx;
    __nv_bfloat16 *ah, *al, *wh, *wl;
    cudaGetSymbolAddress((void**)&gq,   g_q);
    cudaGetSymbolAddress((void**)&gk,   g_k);
    cudaGetSymbolAddress((void**)&gv,   g_v);
    cudaGetSymbolAddress((void**)&gctx, g_ctx);
    cudaGetSymbolAddress((void**)&ah,   g_act_hi);
    cudaGetSymbolAddress((void**)&al,   g_act_lo);
    cudaGetSymbolAddress((void**)&wh,   g_wt_hi);
    cudaGetSymbolAddress((void**)&wl,   g_wt_lo);

    cudaFuncSetAttribute(gemm_mma_kernel,
                         cudaFuncAttributeMaxDynamicSharedMemorySize, GEMM_SMEM);
    const int attn_smem = ATTN_SMEM_FLOATS * 4;
    cudaFuncSetAttribute(attn_kernel,
                         cudaFuncAttributeMaxDynamicSharedMemorySize, attn_smem);

    const int n4 = MROWS * DMODEL / 4;
    dim3 sgrid(n4 / 256);
    dim3 wgrid(DMODEL / 32, DMODEL / 32);
    dim3 ggrid(DMODEL / 128, MROWS / 128);   // (8, 32)

    // Q projection
    split_kernel<<<sgrid, 256>>>(qx, ah, al, n4);
    wtsplit_kernel<<<wgrid, 256>>>(Wq, wh, wl);
    gemm_mma_kernel<<<ggrid, 256, GEMM_SMEM>>>(ah, al, wh, wl, bq, gq);
    // K projection
    split_kernel<<<sgrid, 256>>>(kx, ah, al, n4);
    wtsplit_kernel<<<wgrid, 256>>>(Wk, wh, wl);
    gemm_mma_kernel<<<ggrid, 256, GEMM_SMEM>>>(ah, al, wh, wl, bk, gk);
    // V projection
    split_kernel<<<sgrid, 256>>>(vx, ah, al, n4);
    wtsplit_kernel<<<wgrid, 256>>>(Wv, wh, wl);
    gemm_mma_kernel<<<ggrid, 256, GEMM_SMEM>>>(ah, al, wh, wl, bv, gv);

    // attention
    dim3 agrid(SEQ / BQ, NH, BATCH);
    attn_kernel<<<agrid, 256, attn_smem>>>(gq, gk, gv, gctx);

    // output projection
    split_kernel<<<sgrid, 256>>>(gctx, ah, al, n4);
    wtsplit_kernel<<<wgrid, 256>>>(Wo, wh, wl);
    gemm_mma_kernel<<<ggrid, 256, GEMM_SMEM>>>(ah, al, wh, wl, bo, out);
}

// round 5
// speedup vs baseline: 2.3348x; 1.7496x over previous
#include <cuda_runtime.h>
#include <cuda_bf16.h>
#include <cstdint>
#include <math.h>

#define BATCH 2
#define SEQ   2048
#define NH    16
#define DHEAD 64
#define DMODEL 1024
#define MROWS (BATCH*SEQ)   // 4096

// ---------------- scratch (device globals; no allocation allowed) ----------
__device__ float g_v[MROWS*DMODEL];
__device__ __nv_bfloat16 g_act_hi[MROWS*DMODEL];
__device__ __nv_bfloat16 g_act_lo[MROWS*DMODEL];
__device__ __nv_bfloat16 g_wt_hi[DMODEL*DMODEL];   // W^T layout [N][K]
__device__ __nv_bfloat16 g_wt_lo[DMODEL*DMODEL];
__device__ __nv_bfloat16 g_qh[MROWS*DMODEL];
__device__ __nv_bfloat16 g_ql[MROWS*DMODEL];
__device__ __nv_bfloat16 g_kh[MROWS*DMODEL];
__device__ __nv_bfloat16 g_kl[MROWS*DMODEL];
__device__ __nv_bfloat16 g_vth[MROWS*DMODEL];      // V^T [b][h][d][s]
__device__ __nv_bfloat16 g_vtl[MROWS*DMODEL];

// ======================= helpers ===========================================
__device__ __forceinline__ uint32_t s2u(const void* p) {
    uint32_t a;
    asm("{ .reg .u64 t; cvta.to.shared.u64 t, %1; cvt.u32.u64 %0, t; }"
        : "=r"(a) : "l"(p));
    return a;
}
__device__ __forceinline__ void cp16(uint32_t d, const void* s) {
    asm volatile("cp.async.cg.shared.global [%0], [%1], 16;\n" :: "r"(d), "l"(s));
}
__device__ __forceinline__ void mma_bf16(float* d,
                                         uint32_t a0, uint32_t a1,
                                         uint32_t a2, uint32_t a3,
                                         uint32_t b0, uint32_t b1) {
    asm volatile(
        "mma.sync.aligned.m16n8k16.row.col.f32.bf16.bf16.f32 "
        "{%0,%1,%2,%3}, {%4,%5,%6,%7}, {%8,%9}, {%0,%1,%2,%3};"
        : "+f"(d[0]), "+f"(d[1]), "+f"(d[2]), "+f"(d[3])
        : "r"(a0), "r"(a1), "r"(a2), "r"(a3), "r"(b0), "r"(b1));
}
// split pair (x low, y high) into packed hi-bf16x2 and lo-bf16x2
__device__ __forceinline__ void split2(float x, float y,
                                       uint32_t& hi, uint32_t& lo) {
    __nv_bfloat16 hx = __float2bfloat16(x), hy = __float2bfloat16(y);
    float rx = x - __bfloat162float(hx), ry = y - __bfloat162float(hy);
    __nv_bfloat162 H; H.x = hx; H.y = hy;
    __nv_bfloat162 L; L.x = __float2bfloat16(rx); L.y = __float2bfloat16(ry);
    hi = *(uint32_t*)&H;
    lo = *(uint32_t*)&L;
}

// ======================= split conversion kernels ==========================
__global__ __launch_bounds__(256)
void split_kernel(const float* __restrict__ X,
                  __nv_bfloat16* __restrict__ hi,
                  __nv_bfloat16* __restrict__ lo, int n4)
{
    int i = blockIdx.x * 256 + threadIdx.x;
    if (i >= n4) return;
    float4 v = ((const float4*)X)[i];
    uint32_t h0, l0, h1, l1;
    split2(v.x, v.y, h0, l0);
    split2(v.z, v.w, h1, l1);
    ((uint32_t*)hi)[2*i]   = h0;  ((uint32_t*)hi)[2*i+1] = h1;
    ((uint32_t*)lo)[2*i]   = l0;  ((uint32_t*)lo)[2*i+1] = l1;
}

// transpose + split: W[K,N] -> WT[N,K] as bf16 hi/lo
__global__ __launch_bounds__(256)
void wtsplit_kernel(const float* __restrict__ W,
                    __nv_bfloat16* __restrict__ wth,
                    __nv_bfloat16* __restrict__ wtl)
{
    __shared__ float tile[32][33];
    int tx = threadIdx.x & 31, ty = threadIdx.x >> 5;  // 32x8
    int n0 = blockIdx.x * 32, k0 = blockIdx.y * 32;
#pragma unroll
    for (int i = 0; i < 4; i++)
        tile[ty + 8*i][tx] = W[(size_t)(k0 + ty + 8*i) * DMODEL + n0 + tx];
    __syncthreads();
#pragma unroll
    for (int i = 0; i < 4; i++) {
        float x = tile[tx][ty + 8*i];
        __nv_bfloat16 h = __float2bfloat16(x);
        __nv_bfloat16 l = __float2bfloat16(x - __bfloat162float(h));
        size_t o = (size_t)(n0 + ty + 8*i) * DMODEL + k0 + tx;
        wth[o] = h;
        wtl[o] = l;
    }
}

// transpose + split V: V[b][s][h*64+d] -> Vt[b][h][d][s] bf16 hi/lo
__global__ __launch_bounds__(256)
void vtsplit_kernel(const float* __restrict__ V,
                    __nv_bfloat16* __restrict__ vth,
                    __nv_bfloat16* __restrict__ vtl)
{
    __shared__ float tile[32][33];
    int tx = threadIdx.x & 31, ty = threadIdx.x >> 5;  // 32x8
    int s0 = blockIdx.x * 32, d0 = blockIdx.y * 32, b = blockIdx.z;
#pragma unroll
    for (int i = 0; i < 4; i++)
        tile[ty + 8*i][tx] = V[((size_t)(b*SEQ) + s0 + ty + 8*i) * DMODEL + d0 + tx];
    __syncthreads();
#pragma unroll
    for (int i = 0; i < 4; i++) {
        int d = d0 + ty + 8*i;
        float x = tile[tx][ty + 8*i];
        __nv_bfloat16 h = __float2bfloat16(x);
        __nv_bfloat16 l = __float2bfloat16(x - __bfloat162float(h));
        int hh = d >> 6, dl = d & 63;
        size_t o = (((size_t)(b*NH + hh) * DHEAD + dl)) * SEQ + s0 + tx;
        vth[o] = h;
        vtl[o] = l;
    }
}

// ======================= HMMA GEMM: C = A @ W^T + bias =====================
#define KC 32
#define AST 40
#define TILE_B (128*AST*2)
#define STAGE_B (4*TILE_B)
#define GEMM_SMEM (2*STAGE_B)
#define NCH (DMODEL/KC)

__global__ __launch_bounds__(256)
void gemm_mma_kernel(const __nv_bfloat16* __restrict__ Ah,
                     const __nv_bfloat16* __restrict__ Al,
                     const __nv_bfloat16* __restrict__ Bh,
                     const __nv_bfloat16* __restrict__ Bl,
                     const float* __restrict__ bias,
                     float* __restrict__ C,
                     __nv_bfloat16* __restrict__ Ch,
                     __nv_bfloat16* __restrict__ Cl)
{
    extern __shared__ char smem[];
    const uint32_t sb = s2u(smem);
    const int t = threadIdx.x, w = t >> 5, l = t & 31;
    const int row0 = blockIdx.y * 128, col0 = blockIdx.x * 128;
    const int wm = (w & 1) * 64;
    const int wn = (w >> 1) * 32;

    float acc[4][4][4];
#pragma unroll
    for (int mt = 0; mt < 4; mt++)
#pragma unroll
        for (int nt = 0; nt < 4; nt++)
#pragma unroll
            for (int k = 0; k < 4; k++) acc[mt][nt][k] = 0.f;

    auto load_stage = [&](int c, int st) {
        const uint32_t base = sb + st * STAGE_B;
        const int kc = c * KC;
#pragma unroll
        for (int i = 0; i < 2; i++) {
            int u = t + i * 256;
            int r = u >> 2, j = u & 3;
            uint32_t dso = (uint32_t)(r * 80 + j * 16);
            size_t ga = (size_t)(row0 + r) * DMODEL + kc + j * 8;
            size_t gb = (size_t)(col0 + r) * DMODEL + kc + j * 8;
            cp16(base + dso,              Ah + ga);
            cp16(base + TILE_B + dso,     Al + ga);
            cp16(base + 2*TILE_B + dso,   Bh + gb);
            cp16(base + 3*TILE_B + dso,   Bl + gb);
        }
        asm volatile("cp.async.commit_group;\n" ::: "memory");
    };

    load_stage(0, 0);

    const int ar = l >> 2;
    const int ak = (l & 3) * 2;

    for (int c = 0; c < NCH; c++) {
        if (c + 1 < NCH) {
            load_stage(c + 1, (c + 1) & 1);
            asm volatile("cp.async.wait_group 1;\n" ::: "memory");
        } else {
            asm volatile("cp.async.wait_group 0;\n" ::: "memory");
        }
        __syncthreads();

        const char* stg = smem + (c & 1) * STAGE_B;
        const __nv_bfloat16* sAh = (const __nv_bfloat16*)(stg);
        const __nv_bfloat16* sAl = (const __nv_bfloat16*)(stg + TILE_B);
        const __nv_bfloat16* sBh = (const __nv_bfloat16*)(stg + 2*TILE_B);
        const __nv_bfloat16* sBl = (const __nv_bfloat16*)(stg + 3*TILE_B);

#pragma unroll
        for (int ks = 0; ks < KC; ks += 16) {
            uint32_t aH[4][4], aL[4][4], bH[4][2], bL[4][2];
#pragma unroll
            for (int mt = 0; mt < 4; mt++) {
                int r = wm + mt * 16 + ar;
                const uint32_t* p0 = (const uint32_t*)&sAh[r * AST + ks + ak];
                const uint32_t* p1 = (const uint32_t*)&sAh[(r + 8) * AST + ks + ak];
                aH[mt][0] = p0[0];  aH[mt][1] = p1[0];
                aH[mt][2] = p0[4];  aH[mt][3] = p1[4];
                const uint32_t* q0 = (const uint32_t*)&sAl[r * AST + ks + ak];
                const uint32_t* q1 = (const uint32_t*)&sAl[(r + 8) * AST + ks + ak];
                aL[mt][0] = q0[0];  aL[mt][1] = q1[0];
                aL[mt][2] = q0[4];  aL[mt][3] = q1[4];
            }
#pragma unroll
            for (int nt = 0; nt < 4; nt++) {
                int n = wn + nt * 8 + ar;
                const uint32_t* p = (const uint32_t*)&sBh[n * AST + ks + ak];
                bH[nt][0] = p[0];  bH[nt][1] = p[4];
                const uint32_t* q = (const uint32_t*)&sBl[n * AST + ks + ak];
                bL[nt][0] = q[0];  bL[nt][1] = q[4];
            }
#pragma unroll
            for (int mt = 0; mt < 4; mt++)
#pragma unroll
                for (int nt = 0; nt < 4; nt++) {
                    mma_bf16(acc[mt][nt], aH[mt][0], aH[mt][1], aH[mt][2], aH[mt][3],
                             bH[nt][0], bH[nt][1]);
                    mma_bf16(acc[mt][nt], aL[mt][0], aL[mt][1], aL[mt][2], aL[mt][3],
                             bH[nt][0], bH[nt][1]);
                    mma_bf16(acc[mt][nt], aH[mt][0], aH[mt][1], aH[mt][2], aH[mt][3],
                             bL[nt][0], bL[nt][1]);
                }
        }
        __syncthreads();
    }

#pragma unroll
    for (int mt = 0; mt < 4; mt++) {
        int gr0 = row0 + wm + mt * 16 + ar;
#pragma unroll
        for (int nt = 0; nt < 4; nt++) {
            int gc = col0 + wn + nt * 8 + (l & 3) * 2;
            float b0 = bias[gc], b1 = bias[gc + 1];
            float x0 = acc[mt][nt][0] + b0, y0 = acc[mt][nt][1] + b1;
            float x1 = acc[mt][nt][2] + b0, y1 = acc[mt][nt][3] + b1;
            if (Ch) {
                uint32_t h0, l0w, h1, l1w;
                split2(x0, y0, h0, l0w);
                split2(x1, y1, h1, l1w);
                *(uint32_t*)(Ch + (size_t)gr0 * DMODEL + gc)       = h0;
                *(uint32_t*)(Cl + (size_t)gr0 * DMODEL + gc)       = l0w;
                *(uint32_t*)(Ch + (size_t)(gr0 + 8) * DMODEL + gc) = h1;
                *(uint32_t*)(Cl + (size_t)(gr0 + 8) * DMODEL + gc) = l1w;
            } else {
                *(float2*)(C + (size_t)gr0 * DMODEL + gc)       = make_float2(x0, y0);
                *(float2*)(C + (size_t)(gr0 + 8) * DMODEL + gc) = make_float2(x1, y1);
            }
        }
    }
}

// ======================= HMMA flash attention ==============================
// CTA: (b, h, 128 q-rows). 8 warps x 16 q-rows. KV tiles of 64, dbl-buffered.
#define BQ  128
#define BKV 64
#define NKV (SEQ/BKV)          // 32
#define STB 144                // smem row stride bytes (72 bf16)
#define QTILE_B (128*STB)      // 18432
#define KTILE_B (64*STB)       // 9216
#define STAGE_AB (4*KTILE_B)   // 36864
#define ATTN_SMEM_B (2*QTILE_B + 2*STAGE_AB)   // 110592

__global__ __launch_bounds__(256)
void attn_mma_kernel(const __nv_bfloat16* __restrict__ Qh,
                     const __nv_bfloat16* __restrict__ Ql,
                     const __nv_bfloat16* __restrict__ Kh,
                     const __nv_bfloat16* __restrict__ Kl,
                     const __nv_bfloat16* __restrict__ Vth,
                     const __nv_bfloat16* __restrict__ Vtl,
                     __nv_bfloat16* __restrict__ Oh,
                     __nv_bfloat16* __restrict__ Ol)
{
    extern __shared__ char smem[];
    const uint32_t sb = s2u(smem);
    const int t = threadIdx.x, w = t >> 5, l = t & 31;
    const int q0 = blockIdx.x * BQ;
    const int h  = blockIdx.y, b = blockIdx.z;
    const int r4 = l >> 2;
    const int c4 = (l & 3) * 4;      // byte offset of k-pair within 16-k group

    // ---- prologue: Q hi/lo into smem + stage 0 K/V, one cp.async group ----
    {
        const __nv_bfloat16* QhG = Qh + ((size_t)(b*SEQ + q0)) * DMODEL + h*DHEAD;
        const __nv_bfloat16* QlG = Ql + ((size_t)(b*SEQ + q0)) * DMODEL + h*DHEAD;
#pragma unroll
        for (int i = 0; i < 8; i++) {
            int u = t + i * 256;               // 0..2047
            int tile = u >> 10, v = u & 1023;
            int row = v >> 3, ch = v & 7;
            uint32_t dst = sb + tile * QTILE_B + row * STB + ch * 16;
            const __nv_bfloat16* src = (tile ? QlG : QhG) + (size_t)row * DMODEL + ch * 8;
            cp16(dst, src);
        }
    }
    auto load_kv = [&](int kvt, int st) {
        const uint32_t base = sb + 2*QTILE_B + st * STAGE_AB;
        int kv0 = kvt * BKV;
        const __nv_bfloat16* KhG = Kh + ((size_t)(b*SEQ + kv0)) * DMODEL + h*DHEAD;
        const __nv_bfloat16* KlG = Kl + ((size_t)(b*SEQ + kv0)) * DMODEL + h*DHEAD;
        const __nv_bfloat16* VhG = Vth + ((size_t)(b*NH + h)) * DHEAD * SEQ + kv0;
        const __nv_bfloat16* VlG = Vtl + ((size_t)(b*NH + h)) * DHEAD * SEQ + kv0;
#pragma unroll
        for (int i = 0; i < 8; i++) {
            int u = t + i * 256;               // 0..2047
            int tile = u >> 9, v = u & 511;
            int row = v >> 3, ch = v & 7;
            uint32_t dst = base + tile * KTILE_B + row * STB + ch * 16;
            const __nv_bfloat16* src;
            if      (tile == 0) src = KhG + (size_t)row * DMODEL + ch * 8;
            else if (tile == 1) src = KlG + (size_t)row * DMODEL + ch * 8;
            else if (tile == 2) src = VhG + (size_t)row * SEQ + ch * 8;
            else                src = VlG + (size_t)row * SEQ + ch * 8;
            cp16(dst, src);
        }
        asm volatile("cp.async.commit_group;\n" ::: "memory");
    };
    load_kv(0, 0);
    asm volatile("cp.async.wait_group 0;\n" ::: "memory");
    __syncthreads();

    // ---- Q fragments (held in registers for all kv tiles) ----
    uint32_t aH[4][4], aL[4][4];
    {
        const int qr = w * 16 + r4;
#pragma unroll
        for (int s = 0; s < 4; s++) {
            uint32_t off = qr * STB + 32 * s + c4;
            aH[s][0] = *(const uint32_t*)(smem + off);
            aH[s][1] = *(const uint32_t*)(smem + off + 8*STB);
            aH[s][2] = *(const uint32_t*)(smem + off + 16);
            aH[s][3] = *(const uint32_t*)(smem + off + 8*STB + 16);
            aL[s][0] = *(const uint32_t*)(smem + QTILE_B + off);
            aL[s][1] = *(const uint32_t*)(smem + QTILE_B + off + 8*STB);
            aL[s][2] = *(const uint32_t*)(smem + QTILE_B + off + 16);
            aL[s][3] = *(const uint32_t*)(smem + QTILE_B + off + 8*STB + 16);
        }
    }

    float m0 = -1e30f, m1 = -1e30f, l0 = 0.f, l1 = 0.f;
    float oacc[8][4];
#pragma unroll
    for (int j = 0; j < 8; j++)
#pragma unroll
        for (int k = 0; k < 4; k++) oacc[j][k] = 0.f;

    for (int kvt = 0; kvt < NKV; kvt++) {
        if (kvt + 1 < NKV) {
            load_kv(kvt + 1, (kvt + 1) & 1);
            asm volatile("cp.async.wait_group 1;\n" ::: "memory");
        } else {
            asm volatile("cp.async.wait_group 0;\n" ::: "memory");
        }
        __syncthreads();

        const char* stg = smem + 2*QTILE_B + (kvt & 1) * STAGE_AB;
        const char* sKh = stg;
        const char* sKl = stg + KTILE_B;
        const char* sVh = stg + 2*KTILE_B;
        const char* sVl = stg + 3*KTILE_B;

        // ---- scores: S = (Q*K^T) * 0.125, 3-pass hi/lo ----
        float sc[8][4];
#pragma unroll
        for (int j = 0; j < 8; j++) {
            sc[j][0] = sc[j][1] = sc[j][2] = sc[j][3] = 0.f;
            uint32_t roff = (j * 8 + r4) * STB + c4;
#pragma unroll
            for (int s = 0; s < 4; s++) {
                uint32_t off = roff + 32 * s;
                uint32_t bh0 = *(const uint32_t*)(sKh + off);
                uint32_t bh1 = *(const uint32_t*)(sKh + off + 16);
                uint32_t bl0 = *(const uint32_t*)(sKl + off);
                uint32_t bl1 = *(const uint32_t*)(sKl + off + 16);
                mma_bf16(sc[j], aH[s][0], aH[s][1], aH[s][2], aH[s][3], bh0, bh1);
                mma_bf16(sc[j], aL[s][0], aL[s][1], aL[s][2], aL[s][3], bh0, bh1);
                mma_bf16(sc[j], aH[s][0], aH[s][1], aH[s][2], aH[s][3], bl0, bl1);
            }
        }
#pragma unroll
        for (int j = 0; j < 8; j++)
#pragma unroll
            for (int k = 0; k < 4; k++) sc[j][k] *= 0.125f;

        // ---- online softmax (rows r4 and r4+8 of this warp tile) ----
        float lm0 = -1e30f, lm1 = -1e30f;
#pragma unroll
        for (int j = 0; j < 8; j++) {
            lm0 = fmaxf(lm0, fmaxf(sc[j][0], sc[j][1]));
            lm1 = fmaxf(lm1, fmaxf(sc[j][2], sc[j][3]));
        }
        lm0 = fmaxf(lm0, __shfl_xor_sync(0xffffffffu, lm0, 1));
        lm0 = fmaxf(lm0, __shfl_xor_sync(0xffffffffu, lm0, 2));
        lm1 = fmaxf(lm1, __shfl_xor_sync(0xffffffffu, lm1, 1));
        lm1 = fmaxf(lm1, __shfl_xor_sync(0xffffffffu, lm1, 2));
        float mn0 = fmaxf(m0, lm0), mn1 = fmaxf(m1, lm1);
        float cf0 = __expf(m0 - mn0), cf1 = __expf(m1 - mn1);
        float rs0 = 0.f, rs1 = 0.f;
#pragma unroll
        for (int j = 0; j < 8; j++) {
            float p0 = __expf(sc[j][0] - mn0);
            float p1 = __expf(sc[j][1] - mn0);
            float p2 = __expf(sc[j][2] - mn1);
            float p3 = __expf(sc[j][3] - mn1);
            sc[j][0] = p0; sc[j][1] = p1; sc[j][2] = p2; sc[j][3] = p3;
            rs0 += p0 + p1;  rs1 += p2 + p3;
        }
        rs0 += __shfl_xor_sync(0xffffffffu, rs0, 1);
        rs0 += __shfl_xor_sync(0xffffffffu, rs0, 2);
        rs1 += __shfl_xor_sync(0xffffffffu, rs1, 1);
        rs1 += __shfl_xor_sync(0xffffffffu, rs1, 2);
        l0 = l0 * cf0 + rs0;  l1 = l1 * cf1 + rs1;
        m0 = mn0;  m1 = mn1;
#pragma unroll
        for (int j = 0; j < 8; j++) {
            oacc[j][0] *= cf0;  oacc[j][1] *= cf0;
            oacc[j][2] *= cf1;  oacc[j][3] *= cf1;
        }

        // ---- PV: ctx += P @ V, 3-pass hi/lo; P repacked C->A in registers ----
#pragma unroll
        for (int s = 0; s < 4; s++) {
            uint32_t pH[4], pL[4];
            split2(sc[2*s][0],   sc[2*s][1],   pH[0], pL[0]);
            split2(sc[2*s][2],   sc[2*s][3],   pH[1], pL[1]);
            split2(sc[2*s+1][0], sc[2*s+1][1], pH[2], pL[2]);
            split2(sc[2*s+1][2], sc[2*s+1][3], pH[3], pL[3]);
#pragma unroll
            for (int j = 0; j < 8; j++) {
                uint32_t off = (j * 8 + r4) * STB + 32 * s + c4;
                uint32_t bh0 = *(const uint32_t*)(sVh + off);
                uint32_t bh1 = *(const uint32_t*)(sVh + off + 16);
                uint32_t bl0 = *(const uint32_t*)(sVl + off);
                uint32_t bl1 = *(const uint32_t*)(sVl + off + 16);
                mma_bf16(oacc[j], pH[0], pH[1], pH[2], pH[3], bh0, bh1);
                mma_bf16(oacc[j], pL[0], pL[1], pL[2], pL[3], bh0, bh1);
                mma_bf16(oacc[j], pH[0], pH[1], pH[2], pH[3], bl0, bl1);
            }
        }
        __syncthreads();
    }

    // ---- epilogue: divide by l, split to bf16 hi/lo, write [b,s,h*64+d] ----
    float inv0 = 1.0f / l0, inv1 = 1.0f / l1;
    const size_t rA = (size_t)(b*SEQ + q0 + w*16 + r4) * DMODEL + h*DHEAD + (l & 3) * 2;
    const size_t rB = rA + 8 * DMODEL;
#pragma unroll
    for (int j = 0; j < 8; j++) {
        uint32_t h0, l0w, h1, l1w;
        split2(oacc[j][0] * inv0, oacc[j][1] * inv0, h0, l0w);
        split2(oacc[j][2] * inv1, oacc[j][3] * inv1, h1, l1w);
        *(uint32_t*)(Oh + rA + j*8) = h0;
        *(uint32_t*)(Ol + rA + j*8) = l0w;
        *(uint32_t*)(Oh + rB + j*8) = h1;
        *(uint32_t*)(Ol + rB + j*8) = l1w;
    }
}

// =========================== launch ========================================
extern "C" void kernel_launch(void* const* d_in, const int* in_sizes, int n_in,
                              void* d_out, int out_size)
{
    (void)in_sizes; (void)n_in; (void)out_size;

    const float* qx = (const float*)d_in[0];
    const float* kx = (const float*)d_in[1];
    const float* vx = (const float*)d_in[2];
    const float* Wq = (const float*)d_in[3];
    const float* bq = (const float*)d_in[4];
    const float* Wk = (const float*)d_in[5];
    const float* bk = (const float*)d_in[6];
    const float* Wv = (const float*)d_in[7];
    const float* bv = (const float*)d_in[8];
    const float* Wo = (const float*)d_in[9];
    const float* bo = (const float*)d_in[10];
    float* out = (float*)d_out;

    float *gv;
    __nv_bfloat16 *ah, *al, *wh, *wl, *qh, *ql, *kh, *kl, *vth, *vtl;
    cudaGetSymbolAddress((void**)&gv,  g_v);
    cudaGetSymbolAddress((void**)&ah,  g_act_hi);
    cudaGetSymbolAddress((void**)&al,  g_act_lo);
    cudaGetSymbolAddress((void**)&wh,  g_wt_hi);
    cudaGetSymbolAddress((void**)&wl,  g_wt_lo);
    cudaGetSymbolAddress((void**)&qh,  g_qh);
    cudaGetSymbolAddress((void**)&ql,  g_ql);
    cudaGetSymbolAddress((void**)&kh,  g_kh);
    cudaGetSymbolAddress((void**)&kl,  g_kl);
    cudaGetSymbolAddress((void**)&vth, g_vth);
    cudaGetSymbolAddress((void**)&vtl, g_vtl);

    cudaFuncSetAttribute(gemm_mma_kernel,
                         cudaFuncAttributeMaxDynamicSharedMemorySize, GEMM_SMEM);
    cudaFuncSetAttribute(attn_mma_kernel,
                         cudaFuncAttributeMaxDynamicSharedMemorySize, ATTN_SMEM_B);

    const int n4 = MROWS * DMODEL / 4;
    dim3 sgrid(n4 / 256);
    dim3 wgrid(DMODEL / 32, DMODEL / 32);
    dim3 ggrid(DMODEL / 128, MROWS / 128);
    dim3 vgrid(SEQ / 32, DMODEL / 32, BATCH);

    // Q projection -> bf16 hi/lo directly
    split_kernel<<<sgrid, 256>>>(qx, ah, al, n4);
    wtsplit_kernel<<<wgrid, 256>>>(Wq, wh, wl);
    gemm_mma_kernel<<<ggrid, 256, GEMM_SMEM>>>(ah, al, wh, wl, bq, nullptr, qh, ql);
    // K projection -> bf16 hi/lo directly
    split_kernel<<<sgrid, 256>>>(kx, ah, al, n4);
    wtsplit_kernel<<<wgrid, 256>>>(Wk, wh, wl);
    gemm_mma_kernel<<<ggrid, 256, GEMM_SMEM>>>(ah, al, wh, wl, bk, nullptr, kh, kl);
    // V projection -> fp32, then transpose+split
    split_kernel<<<sgrid, 256>>>(vx, ah, al, n4);
    wtsplit_kernel<<<wgrid, 256>>>(Wv, wh, wl);
    gemm_mma_kernel<<<ggrid, 256, GEMM_SMEM>>>(ah, al, wh, wl, bv, gv, nullptr, nullptr);
    vtsplit_kernel<<<vgrid, 256>>>(gv, vth, vtl);

    // attention -> ctx bf16 hi/lo straight into final-GEMM input buffers
    dim3 agrid(SEQ / BQ, NH, BATCH);
    attn_mma_kernel<<<agrid, 256, ATTN_SMEM_B>>>(qh, ql, kh, kl, vth, vtl, ah, al);

    // output projection -> fp32 out
    wtsplit_kernel<<<wgrid, 256>>>(Wo, wh, wl);
    gemm_mma_kernel<<<ggrid, 256, GEMM_SMEM>>>(ah, al, wh, wl, bo, out, nullptr, nullptr);
}

// round 6
// speedup vs baseline: 2.5924x; 1.1103x over previous
#include <cuda_runtime.h>
#include <cuda_bf16.h>
#include <cstdint>
#include <math.h>

#define BATCH 2
#define SEQ   2048
#define NH    16
#define DHEAD 64
#define DMODEL 1024
#define MROWS (BATCH*SEQ)   // 4096

// ---------------- scratch (device globals; no allocation allowed) ----------
__device__ float g_v[MROWS*DMODEL];
__device__ __nv_bfloat16 g_aqh[MROWS*DMODEL];
__device__ __nv_bfloat16 g_aql[MROWS*DMODEL];
__device__ __nv_bfloat16 g_akh[MROWS*DMODEL];
__device__ __nv_bfloat16 g_akl[MROWS*DMODEL];
__device__ __nv_bfloat16 g_avh[MROWS*DMODEL];
__device__ __nv_bfloat16 g_avl[MROWS*DMODEL];
__device__ __nv_bfloat16 g_wqh[DMODEL*DMODEL];
__device__ __nv_bfloat16 g_wql[DMODEL*DMODEL];
__device__ __nv_bfloat16 g_wkh[DMODEL*DMODEL];
__device__ __nv_bfloat16 g_wkl[DMODEL*DMODEL];
__device__ __nv_bfloat16 g_wvh[DMODEL*DMODEL];
__device__ __nv_bfloat16 g_wvl[DMODEL*DMODEL];
__device__ __nv_bfloat16 g_qh[MROWS*DMODEL];
__device__ __nv_bfloat16 g_ql[MROWS*DMODEL];
__device__ __nv_bfloat16 g_kh[MROWS*DMODEL];
__device__ __nv_bfloat16 g_kl[MROWS*DMODEL];
__device__ __nv_bfloat16 g_vth[MROWS*DMODEL];      // V^T [b][h][d][s]
__device__ __nv_bfloat16 g_vtl[MROWS*DMODEL];

// ======================= helpers ===========================================
__device__ __forceinline__ uint32_t s2u(const void* p) {
    uint32_t a;
    asm("{ .reg .u64 t; cvta.to.shared.u64 t, %1; cvt.u32.u64 %0, t; }"
        : "=r"(a) : "l"(p));
    return a;
}
__device__ __forceinline__ void cp16(uint32_t d, const void* s) {
    asm volatile("cp.async.cg.shared.global [%0], [%1], 16;\n" :: "r"(d), "l"(s));
}
__device__ __forceinline__ void ldsm4(uint32_t* r, uint32_t addr) {
    asm volatile("ldmatrix.sync.aligned.m8n8.x4.shared.b16 {%0,%1,%2,%3}, [%4];"
        : "=r"(r[0]), "=r"(r[1]), "=r"(r[2]), "=r"(r[3]) : "r"(addr));
}
__device__ __forceinline__ void mma_bf16(float* d, const uint32_t* a,
                                         uint32_t b0, uint32_t b1) {
    asm volatile(
        "mma.sync.aligned.m16n8k16.row.col.f32.bf16.bf16.f32 "
        "{%0,%1,%2,%3}, {%4,%5,%6,%7}, {%8,%9}, {%0,%1,%2,%3};"
        : "+f"(d[0]), "+f"(d[1]), "+f"(d[2]), "+f"(d[3])
        : "r"(a[0]), "r"(a[1]), "r"(a[2]), "r"(a[3]), "r"(b0), "r"(b1));
}
// split pair (x low, y high) into packed hi-bf16x2 and lo-bf16x2
__device__ __forceinline__ void split2(float x, float y,
                                       uint32_t& hi, uint32_t& lo) {
    __nv_bfloat16 hx = __float2bfloat16(x), hy = __float2bfloat16(y);
    float rx = x - __bfloat162float(hx), ry = y - __bfloat162float(hy);
    __nv_bfloat162 H; H.x = hx; H.y = hy;
    __nv_bfloat162 L; L.x = __float2bfloat16(rx); L.y = __float2bfloat16(ry);
    hi = *(uint32_t*)&H;
    lo = *(uint32_t*)&L;
}

// ======================= split conversion kernels ==========================
__global__ __launch_bounds__(256)
void split3_kernel(const float* __restrict__ X0, const float* __restrict__ X1,
                   const float* __restrict__ X2,
                   __nv_bfloat16* H0, __nv_bfloat16* L0,
                   __nv_bfloat16* H1, __nv_bfloat16* L1,
                   __nv_bfloat16* H2, __nv_bfloat16* L2, int n4)
{
    int z = blockIdx.y;
    const float* X = z == 0 ? X0 : (z == 1 ? X1 : X2);
    __nv_bfloat16* hi = z == 0 ? H0 : (z == 1 ? H1 : H2);
    __nv_bfloat16* lo = z == 0 ? L0 : (z == 1 ? L1 : L2);
    int i = blockIdx.x * 256 + threadIdx.x;
    if (i >= n4) return;
    float4 v = ((const float4*)X)[i];
    uint32_t h0, l0, h1, l1;
    split2(v.x, v.y, h0, l0);
    split2(v.z, v.w, h1, l1);
    ((uint32_t*)hi)[2*i]   = h0;  ((uint32_t*)hi)[2*i+1] = h1;
    ((uint32_t*)lo)[2*i]   = l0;  ((uint32_t*)lo)[2*i+1] = l1;
}

// transpose + split: W[K,N] -> WT[N,K] as bf16 hi/lo (z selects matrix)
__global__ __launch_bounds__(256)
void wtsplit3_kernel(const float* __restrict__ W0, const float* __restrict__ W1,
                     const float* __restrict__ W2,
                     __nv_bfloat16* H0, __nv_bfloat16* L0,
                     __nv_bfloat16* H1, __nv_bfloat16* L1,
                     __nv_bfloat16* H2, __nv_bfloat16* L2)
{
    int z = blockIdx.z;
    const float* W = z == 0 ? W0 : (z == 1 ? W1 : W2);
    __nv_bfloat16* wth = z == 0 ? H0 : (z == 1 ? H1 : H2);
    __nv_bfloat16* wtl = z == 0 ? L0 : (z == 1 ? L1 : L2);
    __shared__ float tile[32][33];
    int tx = threadIdx.x & 31, ty = threadIdx.x >> 5;  // 32x8
    int n0 = blockIdx.x * 32, k0 = blockIdx.y * 32;
#pragma unroll
    for (int i = 0; i < 4; i++)
        tile[ty + 8*i][tx] = W[(size_t)(k0 + ty + 8*i) * DMODEL + n0 + tx];
    __syncthreads();
#pragma unroll
    for (int i = 0; i < 4; i++) {
        float x = tile[tx][ty + 8*i];
        __nv_bfloat16 h = __float2bfloat16(x);
        __nv_bfloat16 l = __float2bfloat16(x - __bfloat162float(h));
        size_t o = (size_t)(n0 + ty + 8*i) * DMODEL + k0 + tx;
        wth[o] = h;
        wtl[o] = l;
    }
}

// transpose + split V: V[b][s][h*64+d] -> Vt[b][h][d][s] bf16 hi/lo
__global__ __launch_bounds__(256)
void vtsplit_kernel(const float* __restrict__ V,
                    __nv_bfloat16* __restrict__ vth,
                    __nv_bfloat16* __restrict__ vtl)
{
    __shared__ float tile[32][33];
    int tx = threadIdx.x & 31, ty = threadIdx.x >> 5;  // 32x8
    int s0 = blockIdx.x * 32, d0 = blockIdx.y * 32, b = blockIdx.z;
#pragma unroll
    for (int i = 0; i < 4; i++)
        tile[ty + 8*i][tx] = V[((size_t)(b*SEQ) + s0 + ty + 8*i) * DMODEL + d0 + tx];
    __syncthreads();
#pragma unroll
    for (int i = 0; i < 4; i++) {
        int d = d0 + ty + 8*i;
        float x = tile[tx][ty + 8*i];
        __nv_bfloat16 h = __float2bfloat16(x);
        __nv_bfloat16 l = __float2bfloat16(x - __bfloat162float(h));
        int hh = d >> 6, dl = d & 63;
        size_t o = (((size_t)(b*NH + hh) * DHEAD + dl)) * SEQ + s0 + tx;
        vth[o] = h;
        vtl[o] = l;
    }
}

// ======================= HMMA GEMM: C = A @ W^T + bias =====================
#define KC 32
#define AST 40
#define ASTB 80
#define TILE_B (128*AST*2)
#define STAGE_B (4*TILE_B)
#define GEMM_SMEM (2*STAGE_B)
#define NCH (DMODEL/KC)

struct GemmJob {
    const __nv_bfloat16 *Ah, *Al, *Bh, *Bl;
    const float* bias;
    float* C;
    __nv_bfloat16 *Ch, *Cl;
};

__global__ __launch_bounds__(256)
void gemm_mma_kernel(GemmJob j0, GemmJob j1, GemmJob j2)
{
    const GemmJob J = (blockIdx.z == 0) ? j0 : (blockIdx.z == 1 ? j1 : j2);
    extern __shared__ char smem[];
    const uint32_t sb = s2u(smem);
    const int t = threadIdx.x, w = t >> 5, l = t & 31;
    const int row0 = blockIdx.y * 128, col0 = blockIdx.x * 128;
    const int wm = (w & 1) * 64;
    const int wn = (w >> 1) * 32;

    float acc[4][4][4];
#pragma unroll
    for (int mt = 0; mt < 4; mt++)
#pragma unroll
        for (int nt = 0; nt < 4; nt++)
#pragma unroll
            for (int k = 0; k < 4; k++) acc[mt][nt][k] = 0.f;

    auto load_stage = [&](int c, int st) {
        const uint32_t base = sb + st * STAGE_B;
        const int kc = c * KC;
#pragma unroll
        for (int i = 0; i < 2; i++) {
            int u = t + i * 256;
            int r = u >> 2, j = u & 3;
            uint32_t dso = (uint32_t)(r * ASTB + j * 16);
            size_t ga = (size_t)(row0 + r) * DMODEL + kc + j * 8;
            size_t gb = (size_t)(col0 + r) * DMODEL + kc + j * 8;
            cp16(base + dso,              J.Ah + ga);
            cp16(base + TILE_B + dso,     J.Al + ga);
            cp16(base + 2*TILE_B + dso,   J.Bh + gb);
            cp16(base + 3*TILE_B + dso,   J.Bl + gb);
        }
        asm volatile("cp.async.commit_group;\n" ::: "memory");
    };

    load_stage(0, 0);

    // ldmatrix lane geometry
    const int aRow   = (l & 7) + ((l >> 3) & 1) * 8;
    const int aChunk = (l >> 4) * 16;
    const int bRow   = (l & 7) + ((l >> 4) << 3);
    const int bChunk = ((l >> 3) & 1) * 16;

    for (int c = 0; c < NCH; c++) {
        if (c + 1 < NCH) {
            load_stage(c + 1, (c + 1) & 1);
            asm volatile("cp.async.wait_group 1;\n" ::: "memory");
        } else {
            asm volatile("cp.async.wait_group 0;\n" ::: "memory");
        }
        __syncthreads();

        const uint32_t stg = sb + (c & 1) * STAGE_B;
        const uint32_t uAh = stg + (wm + aRow) * ASTB + aChunk;
        const uint32_t uAl = uAh + TILE_B;
        const uint32_t uBh = stg + 2*TILE_B + (wn + bRow) * ASTB + bChunk;
        const uint32_t uBl = uBh + TILE_B;

#pragma unroll
        for (int ks = 0; ks < 2; ks++) {
            const int kb = ks * 32;
            uint32_t aH[4][4], aL[4][4], bH[2][4], bL[2][4];
#pragma unroll
            for (int mt = 0; mt < 4; mt++) {
                ldsm4(aH[mt], uAh + mt * 1280 + kb);
                ldsm4(aL[mt], uAl + mt * 1280 + kb);
            }
#pragma unroll
            for (int p = 0; p < 2; p++) {
                ldsm4(bH[p], uBh + p * 1280 + kb);
                ldsm4(bL[p], uBl + p * 1280 + kb);
            }
#pragma unroll
            for (int mt = 0; mt < 4; mt++)
#pragma unroll
                for (int p = 0; p < 2; p++)
#pragma unroll
                    for (int hf = 0; hf < 2; hf++) {
                        int nt = p * 2 + hf;
                        uint32_t b0h = bH[p][2*hf], b1h = bH[p][2*hf+1];
                        uint32_t b0l = bL[p][2*hf], b1l = bL[p][2*hf+1];
                        mma_bf16(acc[mt][nt], aH[mt], b0h, b1h);
                        mma_bf16(acc[mt][nt], aL[mt], b0h, b1h);
                        mma_bf16(acc[mt][nt], aH[mt], b0l, b1l);
                    }
        }
        __syncthreads();
    }

    const int ar = l >> 2;
#pragma unroll
    for (int mt = 0; mt < 4; mt++) {
        int gr0 = row0 + wm + mt * 16 + ar;
#pragma unroll
        for (int nt = 0; nt < 4; nt++) {
            int gc = col0 + wn + nt * 8 + (l & 3) * 2;
            float b0 = J.bias[gc], b1 = J.bias[gc + 1];
            float x0 = acc[mt][nt][0] + b0, y0 = acc[mt][nt][1] + b1;
            float x1 = acc[mt][nt][2] + b0, y1 = acc[mt][nt][3] + b1;
            if (J.Ch) {
                uint32_t h0, l0w, h1, l1w;
                split2(x0, y0, h0, l0w);
                split2(x1, y1, h1, l1w);
                *(uint32_t*)(J.Ch + (size_t)gr0 * DMODEL + gc)       = h0;
                *(uint32_t*)(J.Cl + (size_t)gr0 * DMODEL + gc)       = l0w;
                *(uint32_t*)(J.Ch + (size_t)(gr0 + 8) * DMODEL + gc) = h1;
                *(uint32_t*)(J.Cl + (size_t)(gr0 + 8) * DMODEL + gc) = l1w;
            } else {
                *(float2*)(J.C + (size_t)gr0 * DMODEL + gc)       = make_float2(x0, y0);
                *(float2*)(J.C + (size_t)(gr0 + 8) * DMODEL + gc) = make_float2(x1, y1);
            }
        }
    }
}

// ======================= HMMA flash attention ==============================
#define BQ  128
#define BKV 64
#define NKV (SEQ/BKV)          // 32
#define STB 144                // smem row stride bytes (72 bf16)
#define QTILE_B (128*STB)      // 18432
#define KTILE_B (64*STB)       // 9216
#define STAGE_AB (4*KTILE_B)   // 36864
#define ATTN_SMEM_B (2*QTILE_B + 2*STAGE_AB)   // 110592

__global__ __launch_bounds__(256)
void attn_mma_kernel(const __nv_bfloat16* __restrict__ Qh,
                     const __nv_bfloat16* __restrict__ Ql,
                     const __nv_bfloat16* __restrict__ Kh,
                     const __nv_bfloat16* __restrict__ Kl,
                     const __nv_bfloat16* __restrict__ Vth,
                     const __nv_bfloat16* __restrict__ Vtl,
                     __nv_bfloat16* __restrict__ Oh,
                     __nv_bfloat16* __restrict__ Ol)
{
    extern __shared__ char smem[];
    const uint32_t sb = s2u(smem);
    const int t = threadIdx.x, w = t >> 5, l = t & 31;
    const int q0 = blockIdx.x * BQ;
    const int h  = blockIdx.y, b = blockIdx.z;
    const int r4 = l >> 2;

    // ---- prologue: Q hi/lo into smem + stage 0 K/V, one cp.async group ----
    {
        const __nv_bfloat16* QhG = Qh + ((size_t)(b*SEQ + q0)) * DMODEL + h*DHEAD;
        const __nv_bfloat16* QlG = Ql + ((size_t)(b*SEQ + q0)) * DMODEL + h*DHEAD;
#pragma unroll
        for (int i = 0; i < 8; i++) {
            int u = t + i * 256;               // 0..2047
            int tile = u >> 10, v = u & 1023;
            int row = v >> 3, ch = v & 7;
            uint32_t dst = sb + tile * QTILE_B + row * STB + ch * 16;
            const __nv_bfloat16* src = (tile ? QlG : QhG) + (size_t)row * DMODEL + ch * 8;
            cp16(dst, src);
        }
    }
    auto load_kv = [&](int kvt, int st) {
        const uint32_t base = sb + 2*QTILE_B + st * STAGE_AB;
        int kv0 = kvt * BKV;
        const __nv_bfloat16* KhG = Kh + ((size_t)(b*SEQ + kv0)) * DMODEL + h*DHEAD;
        const __nv_bfloat16* KlG = Kl + ((size_t)(b*SEQ + kv0)) * DMODEL + h*DHEAD;
        const __nv_bfloat16* VhG = Vth + ((size_t)(b*NH + h)) * DHEAD * SEQ + kv0;
        const __nv_bfloat16* VlG = Vtl + ((size_t)(b*NH + h)) * DHEAD * SEQ + kv0;
#pragma unroll
        for (int i = 0; i < 8; i++) {
            int u = t + i * 256;               // 0..2047
            int tile = u >> 9, v = u & 511;
            int row = v >> 3, ch = v & 7;
            uint32_t dst = base + tile * KTILE_B + row * STB + ch * 16;
            const __nv_bfloat16* src;
            if      (tile == 0) src = KhG + (size_t)row * DMODEL + ch * 8;
            else if (tile == 1) src = KlG + (size_t)row * DMODEL + ch * 8;
            else if (tile == 2) src = VhG + (size_t)row * SEQ + ch * 8;
            else                src = VlG + (size_t)row * SEQ + ch * 8;
            cp16(dst, src);
        }
        asm volatile("cp.async.commit_group;\n" ::: "memory");
    };
    load_kv(0, 0);
    asm volatile("cp.async.wait_group 0;\n" ::: "memory");
    __syncthreads();

    // ldmatrix lane geometry
    const int aRow   = (l & 7) + ((l >> 3) & 1) * 8;
    const int aChunk = (l >> 4) * 16;
    const int bRow   = (l & 7) + ((l >> 4) << 3);
    const int bChunk = ((l >> 3) & 1) * 16;

    // ---- Q fragments (held in registers for all kv tiles) ----
    uint32_t aH[4][4], aL[4][4];
    {
        const uint32_t qoff = sb + (w * 16 + aRow) * STB + aChunk;
#pragma unroll
        for (int s = 0; s < 4; s++) {
            ldsm4(aH[s], qoff + 32 * s);
            ldsm4(aL[s], qoff + QTILE_B + 32 * s);
        }
    }

    float m0 = -1e30f, m1 = -1e30f, l0 = 0.f, l1 = 0.f;
    float oacc[8][4];
#pragma unroll
    for (int j = 0; j < 8; j++)
#pragma unroll
        for (int k = 0; k < 4; k++) oacc[j][k] = 0.f;

    for (int kvt = 0; kvt < NKV; kvt++) {
        if (kvt + 1 < NKV) {
            load_kv(kvt + 1, (kvt + 1) & 1);
            asm volatile("cp.async.wait_group 1;\n" ::: "memory");
        } else {
            asm volatile("cp.async.wait_group 0;\n" ::: "memory");
        }
        __syncthreads();

        const uint32_t stg = sb + 2*QTILE_B + (kvt & 1) * STAGE_AB;
        const uint32_t uKh = stg + bRow * STB + bChunk;
        const uint32_t uKl = uKh + KTILE_B;
        const uint32_t uVh = uKh + 2*KTILE_B;
        const uint32_t uVl = uKh + 3*KTILE_B;

        // ---- scores: S = (Q*K^T) * 0.125, 3-pass hi/lo ----
        float sc[8][4];
#pragma unroll
        for (int j = 0; j < 8; j++)
#pragma unroll
            for (int k = 0; k < 4; k++) sc[j][k] = 0.f;

#pragma unroll
        for (int jp = 0; jp < 4; jp++) {
#pragma unroll
            for (int s = 0; s < 4; s++) {
                uint32_t kh[4], kl[4];
                ldsm4(kh, uKh + jp * 2304 + 32 * s);
                ldsm4(kl, uKl + jp * 2304 + 32 * s);
                mma_bf16(sc[2*jp],   aH[s], kh[0], kh[1]);
                mma_bf16(sc[2*jp],   aL[s], kh[0], kh[1]);
                mma_bf16(sc[2*jp],   aH[s], kl[0], kl[1]);
                mma_bf16(sc[2*jp+1], aH[s], kh[2], kh[3]);
                mma_bf16(sc[2*jp+1], aL[s], kh[2], kh[3]);
                mma_bf16(sc[2*jp+1], aH[s], kl[2], kl[3]);
            }
        }
#pragma unroll
        for (int j = 0; j < 8; j++)
#pragma unroll
            for (int k = 0; k < 4; k++) sc[j][k] *= 0.125f;

        // ---- online softmax (rows r4 and r4+8 of this warp tile) ----
        float lm0 = -1e30f, lm1 = -1e30f;
#pragma unroll
        for (int j = 0; j < 8; j++) {
            lm0 = fmaxf(lm0, fmaxf(sc[j][0], sc[j][1]));
            lm1 = fmaxf(lm1, fmaxf(sc[j][2], sc[j][3]));
        }
        lm0 = fmaxf(lm0, __shfl_xor_sync(0xffffffffu, lm0, 1));
        lm0 = fmaxf(lm0, __shfl_xor_sync(0xffffffffu, lm0, 2));
        lm1 = fmaxf(lm1, __shfl_xor_sync(0xffffffffu, lm1, 1));
        lm1 = fmaxf(lm1, __shfl_xor_sync(0xffffffffu, lm1, 2));
        float mn0 = fmaxf(m0, lm0), mn1 = fmaxf(m1, lm1);
        float cf0 = __expf(m0 - mn0), cf1 = __expf(m1 - mn1);
        float rs0 = 0.f, rs1 = 0.f;
#pragma unroll
        for (int j = 0; j < 8; j++) {
            float p0 = __expf(sc[j][0] - mn0);
            float p1 = __expf(sc[j][1] - mn0);
            float p2 = __expf(sc[j][2] - mn1);
            float p3 = __expf(sc[j][3] - mn1);
            sc[j][0] = p0; sc[j][1] = p1; sc[j][2] = p2; sc[j][3] = p3;
            rs0 += p0 + p1;  rs1 += p2 + p3;
        }
        rs0 += __shfl_xor_sync(0xffffffffu, rs0, 1);
        rs0 += __shfl_xor_sync(0xffffffffu, rs0, 2);
        rs1 += __shfl_xor_sync(0xffffffffu, rs1, 1);
        rs1 += __shfl_xor_sync(0xffffffffu, rs1, 2);
        l0 = l0 * cf0 + rs0;  l1 = l1 * cf1 + rs1;
        m0 = mn0;  m1 = mn1;
#pragma unroll
        for (int j = 0; j < 8; j++) {
            oacc[j][0] *= cf0;  oacc[j][1] *= cf0;
            oacc[j][2] *= cf1;  oacc[j][3] *= cf1;
        }

        // ---- PV: ctx += P @ V, 3-pass hi/lo; P repacked C->A in registers ----
#pragma unroll
        for (int s = 0; s < 4; s++) {
            uint32_t pH[4], pL[4];
            split2(sc[2*s][0],   sc[2*s][1],   pH[0], pL[0]);
            split2(sc[2*s][2],   sc[2*s][3],   pH[1], pL[1]);
            split2(sc[2*s+1][0], sc[2*s+1][1], pH[2], pL[2]);
            split2(sc[2*s+1][2], sc[2*s+1][3], pH[3], pL[3]);
#pragma unroll
            for (int jp = 0; jp < 4; jp++) {
                uint32_t vh[4], vl[4];
                ldsm4(vh, uVh + jp * 2304 + 32 * s);
                ldsm4(vl, uVl + jp * 2304 + 32 * s);
                mma_bf16(oacc[2*jp],   pH, vh[0], vh[1]);
                mma_bf16(oacc[2*jp],   pL, vh[0], vh[1]);
                mma_bf16(oacc[2*jp],   pH, vl[0], vl[1]);
                mma_bf16(oacc[2*jp+1], pH, vh[2], vh[3]);
                mma_bf16(oacc[2*jp+1], pL, vh[2], vh[3]);
                mma_bf16(oacc[2*jp+1], pH, vl[2], vl[3]);
            }
        }
        __syncthreads();
    }

    // ---- epilogue: divide by l, split to bf16 hi/lo, write [b,s,h*64+d] ----
    float inv0 = 1.0f / l0, inv1 = 1.0f / l1;
    const size_t rA = (size_t)(b*SEQ + q0 + w*16 + r4) * DMODEL + h*DHEAD + (l & 3) * 2;
    const size_t rB = rA + 8 * DMODEL;
#pragma unroll
    for (int j = 0; j < 8; j++) {
        uint32_t h0, l0w, h1, l1w;
        split2(oacc[j][0] * inv0, oacc[j][1] * inv0, h0, l0w);
        split2(oacc[j][2] * inv1, oacc[j][3] * inv1, h1, l1w);
        *(uint32_t*)(Oh + rA + j*8) = h0;
        *(uint32_t*)(Ol + rA + j*8) = l0w;
        *(uint32_t*)(Oh + rB + j*8) = h1;
        *(uint32_t*)(Ol + rB + j*8) = l1w;
    }
}

// =========================== launch ========================================
extern "C" void kernel_launch(void* const* d_in, const int* in_sizes, int n_in,
                              void* d_out, int out_size)
{
    (void)in_sizes; (void)n_in; (void)out_size;

    const float* qx = (const float*)d_in[0];
    const float* kx = (const float*)d_in[1];
    const float* vx = (const float*)d_in[2];
    const float* Wq = (const float*)d_in[3];
    const float* bq = (const float*)d_in[4];
    const float* Wk = (const float*)d_in[5];
    const float* bk = (const float*)d_in[6];
    const float* Wv = (const float*)d_in[7];
    const float* bv = (const float*)d_in[8];
    const float* Wo = (const float*)d_in[9];
    const float* bo = (const float*)d_in[10];
    float* out = (float*)d_out;

    float *gv;
    __nv_bfloat16 *aqh, *aql, *akh, *akl, *avh, *avl;
    __nv_bfloat16 *wqh, *wql, *wkh, *wkl, *wvh, *wvl;
    __nv_bfloat16 *qh, *ql, *kh, *kl, *vth, *vtl;
    cudaGetSymbolAddress((void**)&gv,  g_v);
    cudaGetSymbolAddress((void**)&aqh, g_aqh);
    cudaGetSymbolAddress((void**)&aql, g_aql);
    cudaGetSymbolAddress((void**)&akh, g_akh);
    cudaGetSymbolAddress((void**)&akl, g_akl);
    cudaGetSymbolAddress((void**)&avh, g_avh);
    cudaGetSymbolAddress((void**)&avl, g_avl);
    cudaGetSymbolAddress((void**)&wqh, g_wqh);
    cudaGetSymbolAddress((void**)&wql, g_wql);
    cudaGetSymbolAddress((void**)&wkh, g_wkh);
    cudaGetSymbolAddress((void**)&wkl, g_wkl);
    cudaGetSymbolAddress((void**)&wvh, g_wvh);
    cudaGetSymbolAddress((void**)&wvl, g_wvl);
    cudaGetSymbolAddress((void**)&qh,  g_qh);
    cudaGetSymbolAddress((void**)&ql,  g_ql);
    cudaGetSymbolAddress((void**)&kh,  g_kh);
    cudaGetSymbolAddress((void**)&kl,  g_kl);
    cudaGetSymbolAddress((void**)&vth, g_vth);
    cudaGetSymbolAddress((void**)&vtl, g_vtl);

    cudaFuncSetAttribute(gemm_mma_kernel,
                         cudaFuncAttributeMaxDynamicSharedMemorySize, GEMM_SMEM);
    cudaFuncSetAttribute(attn_mma_kernel,
                         cudaFuncAttributeMaxDynamicSharedMemorySize, ATTN_SMEM_B);

    const int n4 = MROWS * DMODEL / 4;

    // fused QKV conversions + projections
    split3_kernel<<<dim3(n4/256, 3), 256>>>(qx, kx, vx,
                                            aqh, aql, akh, akl, avh, avl, n4);
    wtsplit3_kernel<<<dim3(32, 32, 3), 256>>>(Wq, Wk, Wv,
                                              wqh, wql, wkh, wkl, wvh, wvl);
    GemmJob jq = {aqh, aql, wqh, wql, bq, nullptr, qh, ql};
    GemmJob jk = {akh, akl, wkh, wkl, bk, nullptr, kh, kl};
    GemmJob jv = {avh, avl, wvh, wvl, bv, gv, nullptr, nullptr};
    gemm_mma_kernel<<<dim3(8, 32, 3), 256, GEMM_SMEM>>>(jq, jk, jv);
    vtsplit_kernel<<<dim3(SEQ/32, DMODEL/32, BATCH), 256>>>(gv, vth, vtl);

    // attention -> ctx bf16 hi/lo straight into final-GEMM input buffers
    attn_mma_kernel<<<dim3(SEQ/BQ, NH, BATCH), 256, ATTN_SMEM_B>>>(
        qh, ql, kh, kl, vth, vtl, aqh, aql);

    // output projection (reuse wq buffers for Wo)
    wtsplit3_kernel<<<dim3(32, 32, 1), 256>>>(Wo, Wo, Wo,
                                              wqh, wql, wkh, wkl, wvh, wvl);
    GemmJob jo = {aqh, aql, wqh, wql, bo, out, nullptr, nullptr};
    gemm_mma_kernel<<<dim3(8, 32, 1), 256, GEMM_SMEM>>>(jo, jo, jo);
}